// round 1
// baseline (speedup 1.0000x reference)
#include <cuda_runtime.h>
#include <math.h>

#define NN 50000
#define NE 800000
#define ET (NE + NN)          // edges + self loops
#define D 128
#define H 4
#define HD 32
#define NEG 0.2f

// ---------------- scratch (static device globals; no allocation) ----------------
__device__ float g_h[NN * D];      // layer output features
__device__ float g_xw[NN * D];     // GCN x@W
__device__ float g_hgcn[NN * D];   // GCN layer output
__device__ float g_xw2[NN * D];    // GAT x@W
__device__ float g_hatt[NN * D];   // GAT aggregation output
__device__ float g_deg[NN];
__device__ float g_dinv[NN];
__device__ float g_asrc[NN * H];
__device__ float g_adst[NN * H];
__device__ float g_m[NN * H];
__device__ float g_z[NN * H];
__device__ float g_e[ET * H];      // per-edge logits, then exp values

static inline int cdiv(int a, int b) { return (a + b - 1) / b; }

// ---------------- helpers ----------------
__device__ __forceinline__ void red_add_v4(float* p, float4 v) {
    asm volatile("red.global.add.v4.f32 [%0], {%1,%2,%3,%4};"
                 :: "l"(p), "f"(v.x), "f"(v.y), "f"(v.z), "f"(v.w) : "memory");
}

__device__ __forceinline__ void atomicMaxF(float* addr, float v) {
    if (v >= 0.0f) atomicMax((int*)addr, __float_as_int(v));
    else           atomicMin((unsigned int*)addr, __float_as_uint(v));
}

// ---------------- degree / norm ----------------
__global__ void k_zerodeg() {
    int i = blockIdx.x * blockDim.x + threadIdx.x;
    if (i < NN) g_deg[i] = 0.0f;
}

__global__ void k_deg(const int* __restrict__ ei) {
    int e = blockIdx.x * blockDim.x + threadIdx.x;
    if (e >= ET) return;
    int dst = (e < NE) ? ei[NE + e] : (e - NE);
    atomicAdd(&g_deg[dst], 1.0f);
}

__global__ void k_dinv() {
    int i = blockIdx.x * blockDim.x + threadIdx.x;
    if (i < NN) g_dinv[i] = rsqrtf(g_deg[i]);
}

// ---------------- SGEMM: C[M,128] = A[M,128] @ W[128,128] ----------------
// BM=64, BN=128, BK=16, 256 threads, 4x8 register tile per thread.
__global__ void k_gemm(const float* __restrict__ A, const float* __restrict__ W,
                       float* __restrict__ C, int M) {
    __shared__ float As[16][64];
    __shared__ float Bs[16][128];
    const int tid = threadIdx.x;
    const int m0 = blockIdx.x * 64;
    const int ty = tid >> 4;           // 0..15 -> rows ty*4..+3
    const int tx = tid & 15;           // 0..15 -> cols tx*8..+7
    const int lm = tid >> 2;           // 0..63
    const int lk = (tid & 3) << 2;     // 0,4,8,12
    const int bk = tid >> 4;           // 0..15
    const int bc = (tid & 15) << 3;    // 0..120
    float acc[4][8] = {};
    for (int k0 = 0; k0 < 128; k0 += 16) {
        float4 av = make_float4(0.f, 0.f, 0.f, 0.f);
        if (m0 + lm < M) av = *(const float4*)&A[(size_t)(m0 + lm) * D + k0 + lk];
        As[lk + 0][lm] = av.x; As[lk + 1][lm] = av.y;
        As[lk + 2][lm] = av.z; As[lk + 3][lm] = av.w;
        *(float4*)&Bs[bk][bc]     = *(const float4*)&W[(k0 + bk) * D + bc];
        *(float4*)&Bs[bk][bc + 4] = *(const float4*)&W[(k0 + bk) * D + bc + 4];
        __syncthreads();
#pragma unroll
        for (int k = 0; k < 16; k++) {
            float4 ra  = *(const float4*)&As[k][ty * 4];
            float4 rb0 = *(const float4*)&Bs[k][tx * 8];
            float4 rb1 = *(const float4*)&Bs[k][tx * 8 + 4];
            float a_[4] = {ra.x, ra.y, ra.z, ra.w};
            float b_[8] = {rb0.x, rb0.y, rb0.z, rb0.w, rb1.x, rb1.y, rb1.z, rb1.w};
#pragma unroll
            for (int i = 0; i < 4; i++)
#pragma unroll
                for (int j = 0; j < 8; j++)
                    acc[i][j] = fmaf(a_[i], b_[j], acc[i][j]);
        }
        __syncthreads();
    }
#pragma unroll
    for (int i = 0; i < 4; i++) {
        int row = m0 + ty * 4 + i;
        if (row < M) {
            *(float4*)&C[(size_t)row * D + tx * 8] =
                make_float4(acc[i][0], acc[i][1], acc[i][2], acc[i][3]);
            *(float4*)&C[(size_t)row * D + tx * 8 + 4] =
                make_float4(acc[i][4], acc[i][5], acc[i][6], acc[i][7]);
        }
    }
}

// ---------------- broadcast bias into [N, D] buffer ----------------
__global__ void k_bias(float* __restrict__ o, const float* __restrict__ b) {
    int idx = blockIdx.x * blockDim.x + threadIdx.x;   // NN*32 float4 slots
    if (idx >= NN * 32) return;
    ((float4*)o)[idx] = ((const float4*)b)[idx & 31];
}

// ---------------- GCN scatter: hgcn[dst] += xw[src] * dinv[src]*dinv[dst] ----------------
__global__ void k_gcn_scatter(const int* __restrict__ ei) {
    int gt = blockIdx.x * blockDim.x + threadIdx.x;
    int e = gt >> 5, lane = gt & 31;
    if (e >= ET) return;
    int src = (e < NE) ? ei[e]      : (e - NE);
    int dst = (e < NE) ? ei[NE + e] : (e - NE);
    float norm = g_dinv[src] * g_dinv[dst];
    float4 v = ((const float4*)g_xw)[src * 32 + lane];
    v.x *= norm; v.y *= norm; v.z *= norm; v.w *= norm;
    red_add_v4(&g_hgcn[(size_t)dst * D + lane * 4], v);
}

// ---------------- attention coefficients + init m/z ----------------
__global__ void k_attn(const float* __restrict__ ws, const float* __restrict__ wd) {
    int idx = blockIdx.x * blockDim.x + threadIdx.x;   // n*H + h
    if (idx >= NN * H) return;
    int n = idx >> 2, h = idx & 3;
    const float4* xv = (const float4*)&g_xw2[(size_t)n * D + h * HD];
    const float4* as = (const float4*)&ws[h * HD];
    const float4* ad = (const float4*)&wd[h * HD];
    float s = 0.f, d = 0.f;
#pragma unroll
    for (int j = 0; j < 8; j++) {
        float4 x = xv[j], a = as[j], c = ad[j];
        s += x.x * a.x + x.y * a.y + x.z * a.z + x.w * a.w;
        d += x.x * c.x + x.y * c.y + x.z * c.z + x.w * c.w;
    }
    g_asrc[idx] = s;
    g_adst[idx] = d;
    g_m[idx] = -INFINITY;
    g_z[idx] = 0.f;
}

// ---------------- edge pass A: logits + segment max ----------------
__global__ void k_edge_max(const int* __restrict__ ei) {
    int idx = blockIdx.x * blockDim.x + threadIdx.x;   // e*H + h
    if (idx >= ET * H) return;
    int e = idx >> 2, h = idx & 3;
    int src = (e < NE) ? ei[e]      : (e - NE);
    int dst = (e < NE) ? ei[NE + e] : (e - NE);
    float v = g_asrc[src * H + h] + g_adst[dst * H + h];
    v = (v > 0.f) ? v : NEG * v;
    g_e[idx] = v;
    atomicMaxF(&g_m[dst * H + h], v);
}

// ---------------- edge pass B: exp + segment sum ----------------
__global__ void k_edge_exp(const int* __restrict__ ei) {
    int idx = blockIdx.x * blockDim.x + threadIdx.x;
    if (idx >= ET * H) return;
    int e = idx >> 2, h = idx & 3;
    int dst = (e < NE) ? ei[NE + e] : (e - NE);
    float ee = __expf(g_e[idx] - g_m[dst * H + h]);
    g_e[idx] = ee;
    atomicAdd(&g_z[dst * H + h], ee);
}

// ---------------- GAT scatter: hatt[dst] += xw2[src] * alpha ----------------
__global__ void k_gat_scatter(const int* __restrict__ ei) {
    int gt = blockIdx.x * blockDim.x + threadIdx.x;
    int e = gt >> 5, lane = gt & 31;
    if (e >= ET) return;
    int src = (e < NE) ? ei[e]      : (e - NE);
    int dst = (e < NE) ? ei[NE + e] : (e - NE);
    int h = lane >> 3;                        // 8 float4 lanes per head
    float alpha = g_e[e * H + h] / g_z[dst * H + h];
    float4 v = ((const float4*)g_xw2)[src * 32 + lane];
    v.x *= alpha; v.y *= alpha; v.z *= alpha; v.w *= alpha;
    red_add_v4(&g_hatt[(size_t)dst * D + lane * 4], v);
}

// ---------------- LayerNorm(hatt + hgcn) * g + b, then ReLU ----------------
__global__ void k_ln_relu(const float* __restrict__ lg, const float* __restrict__ lb,
                          float* __restrict__ out) {
    int gt = blockIdx.x * blockDim.x + threadIdx.x;
    int n = gt >> 5, lane = gt & 31;
    if (n >= NN) return;
    float4 a = ((const float4*)g_hatt)[n * 32 + lane];
    float4 c = ((const float4*)g_hgcn)[n * 32 + lane];
    a.x += c.x; a.y += c.y; a.z += c.z; a.w += c.w;
    float s = a.x + a.y + a.z + a.w;
#pragma unroll
    for (int o = 16; o; o >>= 1) s += __shfl_xor_sync(0xffffffffu, s, o);
    float mu = s * (1.0f / D);
    float dx = a.x - mu, dy = a.y - mu, dz = a.z - mu, dw = a.w - mu;
    float q = dx * dx + dy * dy + dz * dz + dw * dw;
#pragma unroll
    for (int o = 16; o; o >>= 1) q += __shfl_xor_sync(0xffffffffu, q, o);
    float rs = rsqrtf(q * (1.0f / D) + 1e-5f);
    float4 gg = ((const float4*)lg)[lane];
    float4 bb = ((const float4*)lb)[lane];
    float4 y;
    y.x = fmaxf(dx * rs * gg.x + bb.x, 0.f);
    y.y = fmaxf(dy * rs * gg.y + bb.y, 0.f);
    y.z = fmaxf(dz * rs * gg.z + bb.z, 0.f);
    y.w = fmaxf(dw * rs * gg.w + bb.w, 0.f);
    ((float4*)out)[n * 32 + lane] = y;
}

// ---------------- launch ----------------
extern "C" void kernel_launch(void* const* d_in, const int* in_sizes, int n_in,
                              void* d_out, int out_size) {
    const float* x      = (const float*)d_in[0];
    const int*   ei     = (const int*)  d_in[1];
    const float* gcn_w  = (const float*)d_in[2];
    const float* gcn_b  = (const float*)d_in[3];
    const float* gat_w  = (const float*)d_in[4];
    const float* att_s  = (const float*)d_in[5];
    const float* att_d  = (const float*)d_in[6];
    const float* gat_b  = (const float*)d_in[7];
    const float* ln_g   = (const float*)d_in[8];
    const float* ln_b   = (const float*)d_in[9];
    float* out = (float*)d_out;

    float *p_h, *p_xw, *p_hgcn, *p_xw2, *p_hatt;
    cudaGetSymbolAddress((void**)&p_h,    g_h);
    cudaGetSymbolAddress((void**)&p_xw,   g_xw);
    cudaGetSymbolAddress((void**)&p_hgcn, g_hgcn);
    cudaGetSymbolAddress((void**)&p_xw2,  g_xw2);
    cudaGetSymbolAddress((void**)&p_hatt, g_hatt);

    const int T = 256;
    k_zerodeg<<<cdiv(NN, T), T>>>();
    k_deg<<<cdiv(ET, T), T>>>(ei);
    k_dinv<<<cdiv(NN, T), T>>>();

    const float* hin = x;
    for (int l = 0; l < 3; l++) {
        // GCN
        k_gemm<<<cdiv(NN, 64), T>>>(hin, gcn_w + l * D * D, p_xw, NN);
        k_bias<<<cdiv(NN * 32, T), T>>>(p_hgcn, gcn_b + l * D);
        k_gcn_scatter<<<cdiv(ET * 32, T), T>>>(ei);
        // GAT
        k_gemm<<<cdiv(NN, 64), T>>>(p_hgcn, gat_w + l * D * D, p_xw2, NN);
        k_attn<<<cdiv(NN * H, T), T>>>(att_s + l * H * HD, att_d + l * H * HD);
        k_edge_max<<<cdiv(ET * H, T), T>>>(ei);
        k_edge_exp<<<cdiv(ET * H, T), T>>>(ei);
        k_bias<<<cdiv(NN * 32, T), T>>>(p_hatt, gat_b + l * D);
        k_gat_scatter<<<cdiv(ET * 32, T), T>>>(ei);
        // residual + LN + ReLU
        float* o = (l == 2) ? out : p_h;
        k_ln_relu<<<cdiv(NN * 32, T), T>>>(ln_g + l * D, ln_b + l * D, o);
        hin = p_h;
    }
}

// round 2
// speedup vs baseline: 1.1283x; 1.1283x over previous
#include <cuda_runtime.h>
#include <math.h>

#define NN 50000
#define NE 800000
#define ET (NE + NN)          // edges + self loops
#define D 128
#define H 4
#define HD 32
#define NEG 0.2f

// ---------------- scratch (static device globals; no allocation) ----------------
__device__ float g_h[NN * D];      // layer output features
__device__ float g_xw[NN * D];     // GCN x@W
__device__ float g_hgcn[NN * D];   // GCN layer output
__device__ float g_xw2[NN * D];    // GAT x@W
__device__ float g_dinv[NN];
__device__ float g_asrc[NN * H];
__device__ float g_adst[NN * H];
__device__ int   g_degi[NN];
__device__ int   g_rowptr[NN + 1];
__device__ int   g_cursor[NN];
__device__ int   g_csrc[ET];

static inline int cdiv(int a, int b) { return (a + b - 1) / b; }

// ---------------- CSR build ----------------
__global__ void k_zerodeg() {
    int i = blockIdx.x * blockDim.x + threadIdx.x;
    if (i < NN) g_degi[i] = 0;
}

__global__ void k_deg(const int* __restrict__ ei) {
    int e = blockIdx.x * blockDim.x + threadIdx.x;
    if (e >= ET) return;
    int dst = (e < NE) ? ei[NE + e] : (e - NE);
    atomicAdd(&g_degi[dst], 1);
}

__global__ void k_dinv() {
    int i = blockIdx.x * blockDim.x + threadIdx.x;
    if (i < NN) g_dinv[i] = rsqrtf((float)g_degi[i]);
}

// single-block inclusive scan over degrees -> rowptr (exclusive) + cursor copy
__global__ void k_scan() {
    __shared__ int s[1024];
    __shared__ int carry_s;
    int tid = threadIdx.x;
    if (tid == 0) carry_s = 0;
    __syncthreads();
    for (int base = 0; base < NN; base += 1024) {
        int i = base + tid;
        int v = (i < NN) ? g_degi[i] : 0;
        s[tid] = v;
        __syncthreads();
        for (int off = 1; off < 1024; off <<= 1) {
            int t = (tid >= off) ? s[tid - off] : 0;
            __syncthreads();
            s[tid] += t;
            __syncthreads();
        }
        int incl = s[tid];
        int c = carry_s;
        if (i < NN) {
            g_rowptr[i + 1] = c + incl;
            g_cursor[i]     = c + incl - v;   // exclusive
        }
        __syncthreads();
        if (tid == 1023) carry_s = c + s[1023];
        __syncthreads();
    }
    if (tid == 0) g_rowptr[0] = 0;
}

__global__ void k_fill(const int* __restrict__ ei) {
    int e = blockIdx.x * blockDim.x + threadIdx.x;
    if (e >= ET) return;
    int src = (e < NE) ? ei[e]      : (e - NE);
    int dst = (e < NE) ? ei[NE + e] : (e - NE);
    int pos = atomicAdd(&g_cursor[dst], 1);
    g_csrc[pos] = src;
}

// ---------------- SGEMM: C[M,128] = A[M,128] @ W[128,128] ----------------
// BM=128, BN=128, BK=8, 256 threads, 8x8 register tile, padded smem.
__global__ void __launch_bounds__(256) k_gemm(const float* __restrict__ A,
                                              const float* __restrict__ W,
                                              float* __restrict__ C, int M) {
    __shared__ float As[8][132];
    __shared__ float Bs[8][132];
    const int tid = threadIdx.x;
    const int m0 = blockIdx.x * 128;
    const int ar = tid >> 1;            // 0..127 row in A tile
    const int ac = (tid & 1) * 4;       // 0 or 4 within BK
    const int br = tid >> 5;            // 0..7 k row
    const int bc = (tid & 31) * 4;      // 0..124
    const int ty = tid >> 4;            // 0..15 -> rows ty*8..+7
    const int tx = tid & 15;            // 0..15 -> cols tx*8..+7
    float acc[8][8] = {};
    for (int k0 = 0; k0 < 128; k0 += 8) {
        float4 av = make_float4(0.f, 0.f, 0.f, 0.f);
        if (m0 + ar < M) av = *(const float4*)&A[(size_t)(m0 + ar) * D + k0 + ac];
        As[ac + 0][ar] = av.x; As[ac + 1][ar] = av.y;
        As[ac + 2][ar] = av.z; As[ac + 3][ar] = av.w;
        *(float4*)&Bs[br][bc] = *(const float4*)&W[(k0 + br) * D + bc];
        __syncthreads();
#pragma unroll
        for (int k = 0; k < 8; k++) {
            float a[8], b[8];
            *(float4*)&a[0] = *(const float4*)&As[k][ty * 8];
            *(float4*)&a[4] = *(const float4*)&As[k][ty * 8 + 4];
            *(float4*)&b[0] = *(const float4*)&Bs[k][tx * 8];
            *(float4*)&b[4] = *(const float4*)&Bs[k][tx * 8 + 4];
#pragma unroll
            for (int i = 0; i < 8; i++)
#pragma unroll
                for (int j = 0; j < 8; j++)
                    acc[i][j] = fmaf(a[i], b[j], acc[i][j]);
        }
        __syncthreads();
    }
#pragma unroll
    for (int i = 0; i < 8; i++) {
        int row = m0 + ty * 8 + i;
        if (row < M) {
            *(float4*)&C[(size_t)row * D + tx * 8] =
                make_float4(acc[i][0], acc[i][1], acc[i][2], acc[i][3]);
            *(float4*)&C[(size_t)row * D + tx * 8 + 4] =
                make_float4(acc[i][4], acc[i][5], acc[i][6], acc[i][7]);
        }
    }
}

// ---------------- GCN aggregation (warp per dst, CSR gather) ----------------
__global__ void k_gcn_agg(const float* __restrict__ b) {
    int gt = blockIdx.x * blockDim.x + threadIdx.x;
    int n = gt >> 5, lane = gt & 31;
    if (n >= NN) return;
    const int start = g_rowptr[n], end = g_rowptr[n + 1];
    const float din = g_dinv[n];
    float4 acc = ((const float4*)b)[lane];
    for (int j0 = start; j0 < end; j0 += 32) {
        int jj = j0 + lane;
        int msrc = (jj < end) ? g_csrc[jj] : 0;
        float mnorm = (jj < end) ? g_dinv[msrc] * din : 0.f;
        int cnt = min(32, end - j0);
        for (int t = 0; t < cnt; t++) {
            int   s  = __shfl_sync(0xffffffffu, msrc, t);
            float nm = __shfl_sync(0xffffffffu, mnorm, t);
            float4 v = ((const float4*)g_xw)[s * 32 + lane];
            acc.x = fmaf(v.x, nm, acc.x);
            acc.y = fmaf(v.y, nm, acc.y);
            acc.z = fmaf(v.z, nm, acc.z);
            acc.w = fmaf(v.w, nm, acc.w);
        }
    }
    ((float4*)g_hgcn)[n * 32 + lane] = acc;
}

// ---------------- attention coefficients ----------------
__global__ void k_attn(const float* __restrict__ ws, const float* __restrict__ wd) {
    int idx = blockIdx.x * blockDim.x + threadIdx.x;   // n*H + h
    if (idx >= NN * H) return;
    int n = idx >> 2, h = idx & 3;
    const float4* xv = (const float4*)&g_xw2[(size_t)n * D + h * HD];
    const float4* as = (const float4*)&ws[h * HD];
    const float4* ad = (const float4*)&wd[h * HD];
    float s = 0.f, d = 0.f;
#pragma unroll
    for (int j = 0; j < 8; j++) {
        float4 x = xv[j], a = as[j], c = ad[j];
        s += x.x * a.x + x.y * a.y + x.z * a.z + x.w * a.w;
        d += x.x * c.x + x.y * c.y + x.z * c.z + x.w * c.w;
    }
    g_asrc[idx] = s;
    g_adst[idx] = d;
}

__device__ __forceinline__ float lrelu(float v) { return (v > 0.f) ? v : NEG * v; }

// ---------------- GAT + residual + LayerNorm + ReLU (warp per dst) ----------------
// Softmax without max-subtraction: logits are small (LN-bounded inputs), exp safe;
// exp(e)/sum(exp(e)) is mathematically identical to the max-subtracted form.
__global__ void k_gat_ln(const float* __restrict__ gb, const float* __restrict__ lg,
                         const float* __restrict__ lb, float* __restrict__ out) {
    __shared__ int    s_src[8][32];
    __shared__ float4 s_al[8][32];
    int gt = blockIdx.x * blockDim.x + threadIdx.x;
    int n = gt >> 5, lane = gt & 31, w = threadIdx.x >> 5;
    if (n >= NN) return;
    const int start = g_rowptr[n], end = g_rowptr[n + 1];
    const float4 ad = ((const float4*)g_adst)[n];

    // phase A: z per head (lane-parallel over edges)
    float z0 = 0.f, z1 = 0.f, z2 = 0.f, z3 = 0.f;
    for (int j = start + lane; j < end; j += 32) {
        int src = g_csrc[j];
        float4 as = ((const float4*)g_asrc)[src];
        z0 += __expf(lrelu(as.x + ad.x));
        z1 += __expf(lrelu(as.y + ad.y));
        z2 += __expf(lrelu(as.z + ad.z));
        z3 += __expf(lrelu(as.w + ad.w));
    }
#pragma unroll
    for (int o = 16; o; o >>= 1) {
        z0 += __shfl_xor_sync(0xffffffffu, z0, o);
        z1 += __shfl_xor_sync(0xffffffffu, z1, o);
        z2 += __shfl_xor_sync(0xffffffffu, z2, o);
        z3 += __shfl_xor_sync(0xffffffffu, z3, o);
    }
    const float r0 = 1.f / z0, r1 = 1.f / z1, r2 = 1.f / z2, r3 = 1.f / z3;

    // phase B: weighted gather in 32-edge chunks
    float4 acc = ((const float4*)gb)[lane];
    for (int j0 = start; j0 < end; j0 += 32) {
        int jj = j0 + lane;
        if (jj < end) {
            int src = g_csrc[jj];
            float4 as = ((const float4*)g_asrc)[src];
            float4 al;
            al.x = __expf(lrelu(as.x + ad.x)) * r0;
            al.y = __expf(lrelu(as.y + ad.y)) * r1;
            al.z = __expf(lrelu(as.z + ad.z)) * r2;
            al.w = __expf(lrelu(as.w + ad.w)) * r3;
            s_src[w][lane] = src;
            s_al[w][lane] = al;
        }
        __syncwarp();
        int cnt = min(32, end - j0);
        for (int t = 0; t < cnt; t++) {
            int src = s_src[w][t];
            float a = ((const float*)&s_al[w][t])[lane >> 3];
            float4 v = ((const float4*)g_xw2)[src * 32 + lane];
            acc.x = fmaf(v.x, a, acc.x);
            acc.y = fmaf(v.y, a, acc.y);
            acc.z = fmaf(v.z, a, acc.z);
            acc.w = fmaf(v.w, a, acc.w);
        }
        __syncwarp();
    }

    // residual + LayerNorm + ReLU
    float4 c = ((const float4*)g_hgcn)[n * 32 + lane];
    acc.x += c.x; acc.y += c.y; acc.z += c.z; acc.w += c.w;
    float s = acc.x + acc.y + acc.z + acc.w;
#pragma unroll
    for (int o = 16; o; o >>= 1) s += __shfl_xor_sync(0xffffffffu, s, o);
    float mu = s * (1.0f / D);
    float dx = acc.x - mu, dy = acc.y - mu, dz = acc.z - mu, dw = acc.w - mu;
    float q = dx * dx + dy * dy + dz * dz + dw * dw;
#pragma unroll
    for (int o = 16; o; o >>= 1) q += __shfl_xor_sync(0xffffffffu, q, o);
    float rs = rsqrtf(q * (1.0f / D) + 1e-5f);
    float4 gg = ((const float4*)lg)[lane];
    float4 bb = ((const float4*)lb)[lane];
    float4 y;
    y.x = fmaxf(dx * rs * gg.x + bb.x, 0.f);
    y.y = fmaxf(dy * rs * gg.y + bb.y, 0.f);
    y.z = fmaxf(dz * rs * gg.z + bb.z, 0.f);
    y.w = fmaxf(dw * rs * gg.w + bb.w, 0.f);
    ((float4*)out)[n * 32 + lane] = y;
}

// ---------------- launch ----------------
extern "C" void kernel_launch(void* const* d_in, const int* in_sizes, int n_in,
                              void* d_out, int out_size) {
    const float* x      = (const float*)d_in[0];
    const int*   ei     = (const int*)  d_in[1];
    const float* gcn_w  = (const float*)d_in[2];
    const float* gcn_b  = (const float*)d_in[3];
    const float* gat_w  = (const float*)d_in[4];
    const float* att_s  = (const float*)d_in[5];
    const float* att_d  = (const float*)d_in[6];
    const float* gat_b  = (const float*)d_in[7];
    const float* ln_g   = (const float*)d_in[8];
    const float* ln_b   = (const float*)d_in[9];
    float* out = (float*)d_out;

    float *p_h, *p_xw, *p_hgcn, *p_xw2;
    cudaGetSymbolAddress((void**)&p_h,    g_h);
    cudaGetSymbolAddress((void**)&p_xw,   g_xw);
    cudaGetSymbolAddress((void**)&p_hgcn, g_hgcn);
    cudaGetSymbolAddress((void**)&p_xw2,  g_xw2);

    const int T = 256;
    // CSR build (per replay; graph-capturable, no allocation)
    k_zerodeg<<<cdiv(NN, T), T>>>();
    k_deg<<<cdiv(ET, T), T>>>(ei);
    k_dinv<<<cdiv(NN, T), T>>>();
    k_scan<<<1, 1024>>>();
    k_fill<<<cdiv(ET, T), T>>>(ei);

    const float* hin = x;
    for (int l = 0; l < 3; l++) {
        // GCN
        k_gemm<<<cdiv(NN, 128), T>>>(hin, gcn_w + l * D * D, p_xw, NN);
        k_gcn_agg<<<cdiv(NN * 32, T), T>>>(gcn_b + l * D);
        // GAT
        k_gemm<<<cdiv(NN, 128), T>>>(p_hgcn, gat_w + l * D * D, p_xw2, NN);
        k_attn<<<cdiv(NN * H, T), T>>>(att_s + l * H * HD, att_d + l * H * HD);
        // GAT aggregation + residual + LN + ReLU fused
        float* o = (l == 2) ? out : p_h;
        k_gat_ln<<<cdiv(NN * 32, T), T>>>(gat_b + l * D, ln_g + l * D, ln_b + l * D, o);
        hin = p_h;
    }
}

// round 3
// speedup vs baseline: 1.8362x; 1.6274x over previous
#include <cuda_runtime.h>
#include <math.h>

#define NN 50000
#define NE 800000
#define ET (NE + NN)          // edges + self loops
#define D 128
#define H 4
#define HD 32
#define NEG 0.2f
#define NB 49                 // cdiv(NN, 1024) scan blocks

// ---------------- scratch (static device globals; no allocation) ----------------
__device__ float g_h[NN * D];      // layer output features
__device__ float g_xw[NN * D];     // GCN x@W
__device__ float g_hgcn[NN * D];   // GCN layer output
__device__ float g_xw2[NN * D];    // GAT x@W
__device__ float g_dinv[NN];
__device__ float g_asrc[NN * H];
__device__ float g_adst[NN * H];
__device__ int   g_degi[NN];
__device__ int   g_rowptr[NN + 1];
__device__ int   g_cursor[NN];
__device__ int   g_csrc[ET];
__device__ int   g_bsum[NB];
__device__ int   g_boff[NB];

static inline int cdiv(int a, int b) { return (a + b - 1) / b; }

// ---------------- CSR build ----------------
__global__ void k_zerodeg() {
    int i = blockIdx.x * blockDim.x + threadIdx.x;
    if (i < NN) g_degi[i] = 0;
}

__global__ void k_deg(const int* __restrict__ ei) {
    int e = blockIdx.x * blockDim.x + threadIdx.x;
    if (e >= ET) return;
    int dst = (e < NE) ? ei[NE + e] : (e - NE);
    atomicAdd(&g_degi[dst], 1);
}

// phase 1: per-block (1024 elems, 256 threads x 4) inclusive scan + block sums
__global__ void k_blockscan() {
    __shared__ int wsum[8];
    const int tid = threadIdx.x;
    const int lane = tid & 31, w = tid >> 5;
    const int base = blockIdx.x * 1024 + tid * 4;
    int v[4];
    int s = 0;
#pragma unroll
    for (int j = 0; j < 4; j++) {
        v[j] = (base + j < NN) ? g_degi[base + j] : 0;
        s += v[j];
    }
    int sc = s;  // inclusive warp scan of per-thread sums
#pragma unroll
    for (int o = 1; o < 32; o <<= 1) {
        int t = __shfl_up_sync(0xffffffffu, sc, o);
        if (lane >= o) sc += t;
    }
    if (lane == 31) wsum[w] = sc;
    __syncthreads();
    if (w == 0) {
        int ws = (lane < 8) ? wsum[lane] : 0;
#pragma unroll
        for (int o = 1; o < 8; o <<= 1) {
            int t = __shfl_up_sync(0xffffffffu, ws, o);
            if (lane >= o) ws += t;
        }
        if (lane < 8) wsum[lane] = ws;
    }
    __syncthreads();
    int run = sc - s + (w ? wsum[w - 1] : 0);  // exclusive prefix for this thread
#pragma unroll
    for (int j = 0; j < 4; j++) {
        run += v[j];
        if (base + j < NN) g_rowptr[base + j + 1] = run;  // block-local inclusive
    }
    if (tid == 255) g_bsum[blockIdx.x] = run;  // block total
}

// phase 2: scan the 49 block sums (one tiny block)
__global__ void k_scansums() {
    __shared__ int s[64];
    int tid = threadIdx.x;
    int v = (tid < NB) ? g_bsum[tid] : 0;
    s[tid] = v;
    __syncthreads();
    for (int o = 1; o < 64; o <<= 1) {
        int t = (tid >= o) ? s[tid - o] : 0;
        __syncthreads();
        s[tid] += t;
        __syncthreads();
    }
    if (tid < NB) g_boff[tid] = s[tid] - v;  // exclusive block offset
}

// phase 3: add offsets; derive cursor and dinv
__global__ void k_finalize() {
    int i = blockIdx.x * blockDim.x + threadIdx.x;
    if (i >= NN) return;
    int add = g_boff[i >> 10];
    int deg = g_degi[i];
    int r = g_rowptr[i + 1] + add;
    g_rowptr[i + 1] = r;
    g_cursor[i] = r - deg;
    g_dinv[i] = rsqrtf((float)deg);
    if (i == 0) g_rowptr[0] = 0;
}

__global__ void k_fill(const int* __restrict__ ei) {
    int e = blockIdx.x * blockDim.x + threadIdx.x;
    if (e >= ET) return;
    int src = (e < NE) ? ei[e]      : (e - NE);
    int dst = (e < NE) ? ei[NE + e] : (e - NE);
    int pos = atomicAdd(&g_cursor[dst], 1);
    g_csrc[pos] = src;
}

// ---------------- SGEMM: C[M,128] = A[M,128] @ W[128,128] ----------------
// BM=128, BN=128, BK=8, 256 threads, 8x8 register tile, padded smem.
__global__ void __launch_bounds__(256) k_gemm(const float* __restrict__ A,
                                              const float* __restrict__ W,
                                              float* __restrict__ C, int M) {
    __shared__ float As[8][132];
    __shared__ float Bs[8][132];
    const int tid = threadIdx.x;
    const int m0 = blockIdx.x * 128;
    const int ar = tid >> 1;            // 0..127 row in A tile
    const int ac = (tid & 1) * 4;       // 0 or 4 within BK
    const int br = tid >> 5;            // 0..7 k row
    const int bc = (tid & 31) * 4;      // 0..124
    const int ty = tid >> 4;            // 0..15 -> rows ty*8..+7
    const int tx = tid & 15;            // 0..15 -> cols tx*8..+7
    float acc[8][8] = {};
    for (int k0 = 0; k0 < 128; k0 += 8) {
        float4 av = make_float4(0.f, 0.f, 0.f, 0.f);
        if (m0 + ar < M) av = *(const float4*)&A[(size_t)(m0 + ar) * D + k0 + ac];
        As[ac + 0][ar] = av.x; As[ac + 1][ar] = av.y;
        As[ac + 2][ar] = av.z; As[ac + 3][ar] = av.w;
        *(float4*)&Bs[br][bc] = *(const float4*)&W[(k0 + br) * D + bc];
        __syncthreads();
#pragma unroll
        for (int k = 0; k < 8; k++) {
            float a[8], b[8];
            *(float4*)&a[0] = *(const float4*)&As[k][ty * 8];
            *(float4*)&a[4] = *(const float4*)&As[k][ty * 8 + 4];
            *(float4*)&b[0] = *(const float4*)&Bs[k][tx * 8];
            *(float4*)&b[4] = *(const float4*)&Bs[k][tx * 8 + 4];
#pragma unroll
            for (int i = 0; i < 8; i++)
#pragma unroll
                for (int j = 0; j < 8; j++)
                    acc[i][j] = fmaf(a[i], b[j], acc[i][j]);
        }
        __syncthreads();
    }
#pragma unroll
    for (int i = 0; i < 8; i++) {
        int row = m0 + ty * 8 + i;
        if (row < M) {
            *(float4*)&C[(size_t)row * D + tx * 8] =
                make_float4(acc[i][0], acc[i][1], acc[i][2], acc[i][3]);
            *(float4*)&C[(size_t)row * D + tx * 8 + 4] =
                make_float4(acc[i][4], acc[i][5], acc[i][6], acc[i][7]);
        }
    }
}

// ---------------- GCN aggregation (warp per dst, CSR gather) ----------------
__global__ void k_gcn_agg(const float* __restrict__ b) {
    int gt = blockIdx.x * blockDim.x + threadIdx.x;
    int n = gt >> 5, lane = gt & 31;
    if (n >= NN) return;
    const int start = g_rowptr[n], end = g_rowptr[n + 1];
    const float din = g_dinv[n];
    float4 acc = ((const float4*)b)[lane];
    for (int j0 = start; j0 < end; j0 += 32) {
        int jj = j0 + lane;
        int msrc = (jj < end) ? g_csrc[jj] : 0;
        float mnorm = (jj < end) ? g_dinv[msrc] * din : 0.f;
        int cnt = min(32, end - j0);
        for (int t = 0; t < cnt; t++) {
            int   s  = __shfl_sync(0xffffffffu, msrc, t);
            float nm = __shfl_sync(0xffffffffu, mnorm, t);
            float4 v = ((const float4*)g_xw)[s * 32 + lane];
            acc.x = fmaf(v.x, nm, acc.x);
            acc.y = fmaf(v.y, nm, acc.y);
            acc.z = fmaf(v.z, nm, acc.z);
            acc.w = fmaf(v.w, nm, acc.w);
        }
    }
    ((float4*)g_hgcn)[n * 32 + lane] = acc;
}

// ---------------- attention coefficients ----------------
__global__ void k_attn(const float* __restrict__ ws, const float* __restrict__ wd) {
    int idx = blockIdx.x * blockDim.x + threadIdx.x;   // n*H + h
    if (idx >= NN * H) return;
    int n = idx >> 2, h = idx & 3;
    const float4* xv = (const float4*)&g_xw2[(size_t)n * D + h * HD];
    const float4* as = (const float4*)&ws[h * HD];
    const float4* ad = (const float4*)&wd[h * HD];
    float s = 0.f, d = 0.f;
#pragma unroll
    for (int j = 0; j < 8; j++) {
        float4 x = xv[j], a = as[j], c = ad[j];
        s += x.x * a.x + x.y * a.y + x.z * a.z + x.w * a.w;
        d += x.x * c.x + x.y * c.y + x.z * c.z + x.w * c.w;
    }
    g_asrc[idx] = s;
    g_adst[idx] = d;
}

__device__ __forceinline__ float lrelu(float v) { return (v > 0.f) ? v : NEG * v; }

// ---------------- GAT + residual + LayerNorm + ReLU (warp per dst) ----------------
// Softmax without max-subtraction: logits are small (LN-bounded inputs), exp safe;
// exp(e)/sum(exp(e)) is mathematically identical to the max-subtracted form.
__global__ void k_gat_ln(const float* __restrict__ gb, const float* __restrict__ lg,
                         const float* __restrict__ lb, float* __restrict__ out) {
    __shared__ int    s_src[8][32];
    __shared__ float4 s_al[8][32];
    int gt = blockIdx.x * blockDim.x + threadIdx.x;
    int n = gt >> 5, lane = gt & 31, w = threadIdx.x >> 5;
    if (n >= NN) return;
    const int start = g_rowptr[n], end = g_rowptr[n + 1];
    const float4 ad = ((const float4*)g_adst)[n];

    // phase A: z per head (lane-parallel over edges)
    float z0 = 0.f, z1 = 0.f, z2 = 0.f, z3 = 0.f;
    for (int j = start + lane; j < end; j += 32) {
        int src = g_csrc[j];
        float4 as = ((const float4*)g_asrc)[src];
        z0 += __expf(lrelu(as.x + ad.x));
        z1 += __expf(lrelu(as.y + ad.y));
        z2 += __expf(lrelu(as.z + ad.z));
        z3 += __expf(lrelu(as.w + ad.w));
    }
#pragma unroll
    for (int o = 16; o; o >>= 1) {
        z0 += __shfl_xor_sync(0xffffffffu, z0, o);
        z1 += __shfl_xor_sync(0xffffffffu, z1, o);
        z2 += __shfl_xor_sync(0xffffffffu, z2, o);
        z3 += __shfl_xor_sync(0xffffffffu, z3, o);
    }
    const float r0 = 1.f / z0, r1 = 1.f / z1, r2 = 1.f / z2, r3 = 1.f / z3;

    // phase B: weighted gather in 32-edge chunks
    float4 acc = ((const float4*)gb)[lane];
    for (int j0 = start; j0 < end; j0 += 32) {
        int jj = j0 + lane;
        if (jj < end) {
            int src = g_csrc[jj];
            float4 as = ((const float4*)g_asrc)[src];
            float4 al;
            al.x = __expf(lrelu(as.x + ad.x)) * r0;
            al.y = __expf(lrelu(as.y + ad.y)) * r1;
            al.z = __expf(lrelu(as.z + ad.z)) * r2;
            al.w = __expf(lrelu(as.w + ad.w)) * r3;
            s_src[w][lane] = src;
            s_al[w][lane] = al;
        }
        __syncwarp();
        int cnt = min(32, end - j0);
        for (int t = 0; t < cnt; t++) {
            int src = s_src[w][t];
            float a = ((const float*)&s_al[w][t])[lane >> 3];
            float4 v = ((const float4*)g_xw2)[src * 32 + lane];
            acc.x = fmaf(v.x, a, acc.x);
            acc.y = fmaf(v.y, a, acc.y);
            acc.z = fmaf(v.z, a, acc.z);
            acc.w = fmaf(v.w, a, acc.w);
        }
        __syncwarp();
    }

    // residual + LayerNorm + ReLU
    float4 c = ((const float4*)g_hgcn)[n * 32 + lane];
    acc.x += c.x; acc.y += c.y; acc.z += c.z; acc.w += c.w;
    float s = acc.x + acc.y + acc.z + acc.w;
#pragma unroll
    for (int o = 16; o; o >>= 1) s += __shfl_xor_sync(0xffffffffu, s, o);
    float mu = s * (1.0f / D);
    float dx = acc.x - mu, dy = acc.y - mu, dz = acc.z - mu, dw = acc.w - mu;
    float q = dx * dx + dy * dy + dz * dz + dw * dw;
#pragma unroll
    for (int o = 16; o; o >>= 1) q += __shfl_xor_sync(0xffffffffu, q, o);
    float rs = rsqrtf(q * (1.0f / D) + 1e-5f);
    float4 gg = ((const float4*)lg)[lane];
    float4 bb = ((const float4*)lb)[lane];
    float4 y;
    y.x = fmaxf(dx * rs * gg.x + bb.x, 0.f);
    y.y = fmaxf(dy * rs * gg.y + bb.y, 0.f);
    y.z = fmaxf(dz * rs * gg.z + bb.z, 0.f);
    y.w = fmaxf(dw * rs * gg.w + bb.w, 0.f);
    ((float4*)out)[n * 32 + lane] = y;
}

// ---------------- launch ----------------
extern "C" void kernel_launch(void* const* d_in, const int* in_sizes, int n_in,
                              void* d_out, int out_size) {
    const float* x      = (const float*)d_in[0];
    const int*   ei     = (const int*)  d_in[1];
    const float* gcn_w  = (const float*)d_in[2];
    const float* gcn_b  = (const float*)d_in[3];
    const float* gat_w  = (const float*)d_in[4];
    const float* att_s  = (const float*)d_in[5];
    const float* att_d  = (const float*)d_in[6];
    const float* gat_b  = (const float*)d_in[7];
    const float* ln_g   = (const float*)d_in[8];
    const float* ln_b   = (const float*)d_in[9];
    float* out = (float*)d_out;

    float *p_h, *p_xw, *p_hgcn, *p_xw2;
    cudaGetSymbolAddress((void**)&p_h,    g_h);
    cudaGetSymbolAddress((void**)&p_xw,   g_xw);
    cudaGetSymbolAddress((void**)&p_hgcn, g_hgcn);
    cudaGetSymbolAddress((void**)&p_xw2,  g_xw2);

    const int T = 256;
    // CSR build (per replay; graph-capturable, no allocation)
    k_zerodeg<<<cdiv(NN, T), T>>>();
    k_deg<<<cdiv(ET, T), T>>>(ei);
    k_blockscan<<<NB, 256>>>();
    k_scansums<<<1, 64>>>();
    k_finalize<<<cdiv(NN, T), T>>>();
    k_fill<<<cdiv(ET, T), T>>>(ei);

    const float* hin = x;
    for (int l = 0; l < 3; l++) {
        // GCN
        k_gemm<<<cdiv(NN, 128), T>>>(hin, gcn_w + l * D * D, p_xw, NN);
        k_gcn_agg<<<cdiv(NN * 32, T), T>>>(gcn_b + l * D);
        // GAT
        k_gemm<<<cdiv(NN, 128), T>>>(p_hgcn, gat_w + l * D * D, p_xw2, NN);
        k_attn<<<cdiv(NN * H, T), T>>>(att_s + l * H * HD, att_d + l * H * HD);
        // GAT aggregation + residual + LN + ReLU fused
        float* o = (l == 2) ? out : p_h;
        k_gat_ln<<<cdiv(NN * 32, T), T>>>(gat_b + l * D, ln_g + l * D, ln_b + l * D, o);
        hin = p_h;
    }
}

// round 4
// speedup vs baseline: 2.1966x; 1.1963x over previous
#include <cuda_runtime.h>
#include <math.h>
#include <stdint.h>

#define NN 50000
#define NE 800000
#define ET (NE + NN)          // edges + self loops
#define D 128
#define H 4
#define HD 32
#define NEG 0.2f
#define NB 49                 // cdiv(NN, 1024) scan blocks

// ---------------- scratch (static device globals; no allocation) ----------------
__device__ float g_h[NN * D];      // layer output features
__device__ float g_xw[NN * D];     // GCN x@W
__device__ float g_hgcn[NN * D];   // GCN layer output
__device__ float g_xw2[NN * D];    // GAT x@W
__device__ float g_dinv[NN];
__device__ float g_asrc[NN * H];
__device__ float g_adst[NN * H];
__device__ int   g_degi[NN];
__device__ int   g_rowptr[NN + 1];
__device__ int   g_cursor[NN];
__device__ int   g_csrc[ET];
__device__ int   g_bsum[NB];
__device__ int   g_boff[NB];

static inline int cdiv(int a, int b) { return (a + b - 1) / b; }

// ---------------- CSR build ----------------
__global__ void k_zerodeg() {
    int i = blockIdx.x * blockDim.x + threadIdx.x;
    if (i < NN) g_degi[i] = 0;
}

__global__ void k_deg(const int* __restrict__ ei) {
    int e = blockIdx.x * blockDim.x + threadIdx.x;
    if (e >= ET) return;
    int dst = (e < NE) ? ei[NE + e] : (e - NE);
    atomicAdd(&g_degi[dst], 1);
}

// phase 1: per-block (1024 elems, 256 threads x 4) inclusive scan + block sums
__global__ void k_blockscan() {
    __shared__ int wsum[8];
    const int tid = threadIdx.x;
    const int lane = tid & 31, w = tid >> 5;
    const int base = blockIdx.x * 1024 + tid * 4;
    int v[4];
    int s = 0;
#pragma unroll
    for (int j = 0; j < 4; j++) {
        v[j] = (base + j < NN) ? g_degi[base + j] : 0;
        s += v[j];
    }
    int sc = s;  // inclusive warp scan of per-thread sums
#pragma unroll
    for (int o = 1; o < 32; o <<= 1) {
        int t = __shfl_up_sync(0xffffffffu, sc, o);
        if (lane >= o) sc += t;
    }
    if (lane == 31) wsum[w] = sc;
    __syncthreads();
    if (w == 0) {
        int ws = (lane < 8) ? wsum[lane] : 0;
#pragma unroll
        for (int o = 1; o < 8; o <<= 1) {
            int t = __shfl_up_sync(0xffffffffu, ws, o);
            if (lane >= o) ws += t;
        }
        if (lane < 8) wsum[lane] = ws;
    }
    __syncthreads();
    int run = sc - s + (w ? wsum[w - 1] : 0);  // exclusive prefix for this thread
#pragma unroll
    for (int j = 0; j < 4; j++) {
        run += v[j];
        if (base + j < NN) g_rowptr[base + j + 1] = run;  // block-local inclusive
    }
    if (tid == 255) g_bsum[blockIdx.x] = run;  // block total
}

// phase 2: scan the 49 block sums (one tiny block)
__global__ void k_scansums() {
    __shared__ int s[64];
    int tid = threadIdx.x;
    int v = (tid < NB) ? g_bsum[tid] : 0;
    s[tid] = v;
    __syncthreads();
    for (int o = 1; o < 64; o <<= 1) {
        int t = (tid >= o) ? s[tid - o] : 0;
        __syncthreads();
        s[tid] += t;
        __syncthreads();
    }
    if (tid < NB) g_boff[tid] = s[tid] - v;  // exclusive block offset
}

// phase 3: add offsets; derive cursor and dinv
__global__ void k_finalize() {
    int i = blockIdx.x * blockDim.x + threadIdx.x;
    if (i >= NN) return;
    int add = g_boff[i >> 10];
    int deg = g_degi[i];
    int r = g_rowptr[i + 1] + add;
    g_rowptr[i + 1] = r;
    g_cursor[i] = r - deg;
    g_dinv[i] = rsqrtf((float)deg);
    if (i == 0) g_rowptr[0] = 0;
}

__global__ void k_fill(const int* __restrict__ ei) {
    int e = blockIdx.x * blockDim.x + threadIdx.x;
    if (e >= ET) return;
    int src = (e < NE) ? ei[e]      : (e - NE);
    int dst = (e < NE) ? ei[NE + e] : (e - NE);
    int pos = atomicAdd(&g_cursor[dst], 1);
    g_csrc[pos] = src;
}

// ---------------- tf32 tensor-core GEMM: C[M,128] = A[M,128] @ W[128,128] ----
// BM=128, BN=128, BK=16. 256 threads = 8 warps in 4(M)x2(N); warp tile 32x64.
// mma.sync m16n8k8 tf32, fp32 accum. Fragment-packed smem: A frag = 1 LDS.128,
// B frag = 1 LDS.64, conflict-free.

__device__ __forceinline__ uint32_t f2tf32(float x) {
    uint32_t r;
    asm("cvt.rna.tf32.f32 %0, %1;" : "=r"(r) : "f"(x));
    return r;
}

__device__ __forceinline__ void mma_tf32(float* c, const uint32_t* a, const uint32_t* b) {
    asm volatile(
        "mma.sync.aligned.m16n8k8.row.col.f32.tf32.tf32.f32 "
        "{%0,%1,%2,%3}, {%4,%5,%6,%7}, {%8,%9}, {%0,%1,%2,%3};"
        : "+f"(c[0]), "+f"(c[1]), "+f"(c[2]), "+f"(c[3])
        : "r"(a[0]), "r"(a[1]), "r"(a[2]), "r"(a[3]), "r"(b[0]), "r"(b[1]));
}

__global__ void __launch_bounds__(256) k_gemm(const float* __restrict__ A,
                                              const float* __restrict__ W,
                                              float* __restrict__ C, int M) {
    // As[kf][mf][lane][slot]: element (m,k): mf=m>>4, mr=m&15, kf=k>>3, kk=k&7
    //   lane = (mr&7)*4 + (kk&3), slot = (mr>>3) | ((kk>>2)<<1)
    // Bs[kf][nf][lane][slot]: element (k,n): nf=n>>3, nr=n&7
    //   lane = nr*4 + (kk&3), slot = kk>>2
    __shared__ uint32_t As[2][8][32][4];
    __shared__ uint32_t Bs[2][16][32][2];
    const int tid = threadIdx.x;
    const int lane = tid & 31;
    const int warp = tid >> 5;
    const int wm = warp >> 1;       // 0..3
    const int wn = warp & 1;        // 0..1
    const int m0 = blockIdx.x * 128;

    float acc[2][8][4];
#pragma unroll
    for (int i = 0; i < 2; i++)
#pragma unroll
        for (int j = 0; j < 8; j++)
#pragma unroll
            for (int q = 0; q < 4; q++) acc[i][j][q] = 0.f;

    for (int k0 = 0; k0 < 128; k0 += 16) {
        // stage A chunk (128 x 16): 512 float4, 2 per thread
#pragma unroll
        for (int i = 0; i < 2; i++) {
            int f = tid * 2 + i;
            int row = f >> 2;
            int c4 = (f & 3) * 4;
            float4 v = make_float4(0.f, 0.f, 0.f, 0.f);
            if (m0 + row < M) v = *(const float4*)&A[(size_t)(m0 + row) * D + k0 + c4];
            int mf = row >> 4, mr = row & 15;
            float vv[4] = {v.x, v.y, v.z, v.w};
#pragma unroll
            for (int j = 0; j < 4; j++) {
                int k = c4 + j;
                int kf = k >> 3, kk = k & 7;
                As[kf][mf][(mr & 7) * 4 + (kk & 3)][(mr >> 3) | ((kk >> 2) << 1)] = f2tf32(vv[j]);
            }
        }
        // stage B chunk (16 x 128): 512 float4, 2 per thread
#pragma unroll
        for (int i = 0; i < 2; i++) {
            int f = tid * 2 + i;
            int kl = f >> 5;
            int n4 = (f & 31) * 4;
            float4 v = *(const float4*)&W[(size_t)(k0 + kl) * D + n4];
            int kf = kl >> 3, kk = kl & 7;
            float vv[4] = {v.x, v.y, v.z, v.w};
#pragma unroll
            for (int j = 0; j < 4; j++) {
                int n = n4 + j;
                Bs[kf][n >> 3][(n & 7) * 4 + (kk & 3)][kk >> 2] = f2tf32(vv[j]);
            }
        }
        __syncthreads();
#pragma unroll
        for (int kf = 0; kf < 2; kf++) {
            uint32_t afr[2][4];
#pragma unroll
            for (int mf = 0; mf < 2; mf++) {
                uint4 t = *(const uint4*)&As[kf][wm * 2 + mf][lane][0];
                afr[mf][0] = t.x; afr[mf][1] = t.y; afr[mf][2] = t.z; afr[mf][3] = t.w;
            }
            uint32_t bfr[8][2];
#pragma unroll
            for (int nf = 0; nf < 8; nf++) {
                uint2 t = *(const uint2*)&Bs[kf][wn * 8 + nf][lane][0];
                bfr[nf][0] = t.x; bfr[nf][1] = t.y;
            }
#pragma unroll
            for (int mf = 0; mf < 2; mf++)
#pragma unroll
                for (int nf = 0; nf < 8; nf++)
                    mma_tf32(acc[mf][nf], afr[mf], bfr[nf]);
        }
        __syncthreads();
    }

    // epilogue: c0,c1 at (g, q*2), c2,c3 at (g+8, q*2)
    const int g = lane >> 2, q = lane & 3;
#pragma unroll
    for (int mf = 0; mf < 2; mf++) {
        int row0 = m0 + wm * 32 + mf * 16 + g;
        int row1 = row0 + 8;
#pragma unroll
        for (int nf = 0; nf < 8; nf++) {
            int col = wn * 64 + nf * 8 + q * 2;
            if (row0 < M) *(float2*)&C[(size_t)row0 * D + col] = make_float2(acc[mf][nf][0], acc[mf][nf][1]);
            if (row1 < M) *(float2*)&C[(size_t)row1 * D + col] = make_float2(acc[mf][nf][2], acc[mf][nf][3]);
        }
    }
}

// ---------------- GCN aggregation (warp per dst, CSR gather) ----------------
__global__ void k_gcn_agg(const float* __restrict__ b) {
    int gt = blockIdx.x * blockDim.x + threadIdx.x;
    int n = gt >> 5, lane = gt & 31;
    if (n >= NN) return;
    const int start = g_rowptr[n], end = g_rowptr[n + 1];
    const float din = g_dinv[n];
    float4 acc = ((const float4*)b)[lane];
    for (int j0 = start; j0 < end; j0 += 32) {
        int jj = j0 + lane;
        int msrc = (jj < end) ? g_csrc[jj] : 0;
        float mnorm = (jj < end) ? g_dinv[msrc] * din : 0.f;
        int cnt = min(32, end - j0);
        for (int t = 0; t < cnt; t++) {
            int   s  = __shfl_sync(0xffffffffu, msrc, t);
            float nm = __shfl_sync(0xffffffffu, mnorm, t);
            float4 v = ((const float4*)g_xw)[s * 32 + lane];
            acc.x = fmaf(v.x, nm, acc.x);
            acc.y = fmaf(v.y, nm, acc.y);
            acc.z = fmaf(v.z, nm, acc.z);
            acc.w = fmaf(v.w, nm, acc.w);
        }
    }
    ((float4*)g_hgcn)[n * 32 + lane] = acc;
}

// ---------------- attention coefficients ----------------
__global__ void k_attn(const float* __restrict__ ws, const float* __restrict__ wd) {
    int idx = blockIdx.x * blockDim.x + threadIdx.x;   // n*H + h
    if (idx >= NN * H) return;
    int n = idx >> 2, h = idx & 3;
    const float4* xv = (const float4*)&g_xw2[(size_t)n * D + h * HD];
    const float4* as = (const float4*)&ws[h * HD];
    const float4* ad = (const float4*)&wd[h * HD];
    float s = 0.f, d = 0.f;
#pragma unroll
    for (int j = 0; j < 8; j++) {
        float4 x = xv[j], a = as[j], c = ad[j];
        s += x.x * a.x + x.y * a.y + x.z * a.z + x.w * a.w;
        d += x.x * c.x + x.y * c.y + x.z * c.z + x.w * c.w;
    }
    g_asrc[idx] = s;
    g_adst[idx] = d;
}

__device__ __forceinline__ float lrelu(float v) { return (v > 0.f) ? v : NEG * v; }

// ---------------- GAT + residual + LayerNorm + ReLU (warp per dst) ----------------
// Softmax without max-subtraction: logits are small (LN-bounded inputs), exp safe;
// exp(e)/sum(exp(e)) is mathematically identical to the max-subtracted form.
__global__ void k_gat_ln(const float* __restrict__ gb, const float* __restrict__ lg,
                         const float* __restrict__ lb, float* __restrict__ out) {
    __shared__ int    s_src[8][32];
    __shared__ float4 s_al[8][32];
    int gt = blockIdx.x * blockDim.x + threadIdx.x;
    int n = gt >> 5, lane = gt & 31, w = threadIdx.x >> 5;
    if (n >= NN) return;
    const int start = g_rowptr[n], end = g_rowptr[n + 1];
    const float4 ad = ((const float4*)g_adst)[n];

    // phase A: z per head (lane-parallel over edges)
    float z0 = 0.f, z1 = 0.f, z2 = 0.f, z3 = 0.f;
    for (int j = start + lane; j < end; j += 32) {
        int src = g_csrc[j];
        float4 as = ((const float4*)g_asrc)[src];
        z0 += __expf(lrelu(as.x + ad.x));
        z1 += __expf(lrelu(as.y + ad.y));
        z2 += __expf(lrelu(as.z + ad.z));
        z3 += __expf(lrelu(as.w + ad.w));
    }
#pragma unroll
    for (int o = 16; o; o >>= 1) {
        z0 += __shfl_xor_sync(0xffffffffu, z0, o);
        z1 += __shfl_xor_sync(0xffffffffu, z1, o);
        z2 += __shfl_xor_sync(0xffffffffu, z2, o);
        z3 += __shfl_xor_sync(0xffffffffu, z3, o);
    }
    const float r0 = 1.f / z0, r1 = 1.f / z1, r2 = 1.f / z2, r3 = 1.f / z3;

    // phase B: weighted gather in 32-edge chunks
    float4 acc = ((const float4*)gb)[lane];
    for (int j0 = start; j0 < end; j0 += 32) {
        int jj = j0 + lane;
        if (jj < end) {
            int src = g_csrc[jj];
            float4 as = ((const float4*)g_asrc)[src];
            float4 al;
            al.x = __expf(lrelu(as.x + ad.x)) * r0;
            al.y = __expf(lrelu(as.y + ad.y)) * r1;
            al.z = __expf(lrelu(as.z + ad.z)) * r2;
            al.w = __expf(lrelu(as.w + ad.w)) * r3;
            s_src[w][lane] = src;
            s_al[w][lane] = al;
        }
        __syncwarp();
        int cnt = min(32, end - j0);
        for (int t = 0; t < cnt; t++) {
            int src = s_src[w][t];
            float a = ((const float*)&s_al[w][t])[lane >> 3];
            float4 v = ((const float4*)g_xw2)[src * 32 + lane];
            acc.x = fmaf(v.x, a, acc.x);
            acc.y = fmaf(v.y, a, acc.y);
            acc.z = fmaf(v.z, a, acc.z);
            acc.w = fmaf(v.w, a, acc.w);
        }
        __syncwarp();
    }

    // residual + LayerNorm + ReLU
    float4 c = ((const float4*)g_hgcn)[n * 32 + lane];
    acc.x += c.x; acc.y += c.y; acc.z += c.z; acc.w += c.w;
    float s = acc.x + acc.y + acc.z + acc.w;
#pragma unroll
    for (int o = 16; o; o >>= 1) s += __shfl_xor_sync(0xffffffffu, s, o);
    float mu = s * (1.0f / D);
    float dx = acc.x - mu, dy = acc.y - mu, dz = acc.z - mu, dw = acc.w - mu;
    float q = dx * dx + dy * dy + dz * dz + dw * dw;
#pragma unroll
    for (int o = 16; o; o >>= 1) q += __shfl_xor_sync(0xffffffffu, q, o);
    float rs = rsqrtf(q * (1.0f / D) + 1e-5f);
    float4 gg = ((const float4*)lg)[lane];
    float4 bb = ((const float4*)lb)[lane];
    float4 y;
    y.x = fmaxf(dx * rs * gg.x + bb.x, 0.f);
    y.y = fmaxf(dy * rs * gg.y + bb.y, 0.f);
    y.z = fmaxf(dz * rs * gg.z + bb.z, 0.f);
    y.w = fmaxf(dw * rs * gg.w + bb.w, 0.f);
    ((float4*)out)[n * 32 + lane] = y;
}

// ---------------- launch ----------------
extern "C" void kernel_launch(void* const* d_in, const int* in_sizes, int n_in,
                              void* d_out, int out_size) {
    const float* x      = (const float*)d_in[0];
    const int*   ei     = (const int*)  d_in[1];
    const float* gcn_w  = (const float*)d_in[2];
    const float* gcn_b  = (const float*)d_in[3];
    const float* gat_w  = (const float*)d_in[4];
    const float* att_s  = (const float*)d_in[5];
    const float* att_d  = (const float*)d_in[6];
    const float* gat_b  = (const float*)d_in[7];
    const float* ln_g   = (const float*)d_in[8];
    const float* ln_b   = (const float*)d_in[9];
    float* out = (float*)d_out;

    float *p_h, *p_xw, *p_hgcn, *p_xw2;
    cudaGetSymbolAddress((void**)&p_h,    g_h);
    cudaGetSymbolAddress((void**)&p_xw,   g_xw);
    cudaGetSymbolAddress((void**)&p_hgcn, g_hgcn);
    cudaGetSymbolAddress((void**)&p_xw2,  g_xw2);

    const int T = 256;
    // CSR build (per replay; graph-capturable, no allocation)
    k_zerodeg<<<cdiv(NN, T), T>>>();
    k_deg<<<cdiv(ET, T), T>>>(ei);
    k_blockscan<<<NB, 256>>>();
    k_scansums<<<1, 64>>>();
    k_finalize<<<cdiv(NN, T), T>>>();
    k_fill<<<cdiv(ET, T), T>>>(ei);

    const float* hin = x;
    for (int l = 0; l < 3; l++) {
        // GCN
        k_gemm<<<cdiv(NN, 128), T>>>(hin, gcn_w + l * D * D, p_xw, NN);
        k_gcn_agg<<<cdiv(NN * 32, T), T>>>(gcn_b + l * D);
        // GAT
        k_gemm<<<cdiv(NN, 128), T>>>(p_hgcn, gat_w + l * D * D, p_xw2, NN);
        k_attn<<<cdiv(NN * H, T), T>>>(att_s + l * H * HD, att_d + l * H * HD);
        // GAT aggregation + residual + LN + ReLU fused
        float* o = (l == 2) ? out : p_h;
        k_gat_ln<<<cdiv(NN * 32, T), T>>>(gat_b + l * D, ln_g + l * D, ln_b + l * D, o);
        hin = p_h;
    }
}

// round 5
// speedup vs baseline: 2.4845x; 1.1311x over previous
#include <cuda_runtime.h>
#include <cuda_fp16.h>
#include <math.h>
#include <stdint.h>

#define NN 50000
#define NE 800000
#define ET (NE + NN)          // edges + self loops
#define D 128
#define H 4
#define HD 32
#define NEG 0.2f
#define NB 49                 // cdiv(NN, 1024) scan blocks

// ---------------- scratch (static device globals; no allocation) ----------------
__device__ float  g_h[NN * D];      // layer output features (fp32)
__device__ __half g_xwh[NN * D];    // GCN x@W  (fp16, gathered)
__device__ float  g_hgcn[NN * D];   // GCN layer output (fp32)
__device__ __half g_xw2h[NN * D];   // GAT x@W  (fp16, gathered)
__device__ float  g_dinv[NN];
__device__ float  g_asrc[NN * H];
__device__ float  g_adst[NN * H];
__device__ int    g_degi[NN];
__device__ int    g_rowptr[NN + 1];
__device__ int    g_cursor[NN];
__device__ int    g_csrc[ET];
__device__ int    g_bsum[NB];
__device__ int    g_boff[NB];

static inline int cdiv(int a, int b) { return (a + b - 1) / b; }

// ---------------- CSR build ----------------
__global__ void k_zerodeg() {
    int i = blockIdx.x * blockDim.x + threadIdx.x;
    if (i < NN) g_degi[i] = 0;
}

__global__ void k_deg(const int* __restrict__ ei) {
    int e = blockIdx.x * blockDim.x + threadIdx.x;
    if (e >= ET) return;
    int dst = (e < NE) ? ei[NE + e] : (e - NE);
    atomicAdd(&g_degi[dst], 1);
}

// phase 1: per-block (1024 elems, 256 threads x 4) inclusive scan + block sums
__global__ void k_blockscan() {
    __shared__ int wsum[8];
    const int tid = threadIdx.x;
    const int lane = tid & 31, w = tid >> 5;
    const int base = blockIdx.x * 1024 + tid * 4;
    int v[4];
    int s = 0;
#pragma unroll
    for (int j = 0; j < 4; j++) {
        v[j] = (base + j < NN) ? g_degi[base + j] : 0;
        s += v[j];
    }
    int sc = s;  // inclusive warp scan of per-thread sums
#pragma unroll
    for (int o = 1; o < 32; o <<= 1) {
        int t = __shfl_up_sync(0xffffffffu, sc, o);
        if (lane >= o) sc += t;
    }
    if (lane == 31) wsum[w] = sc;
    __syncthreads();
    if (w == 0) {
        int ws = (lane < 8) ? wsum[lane] : 0;
#pragma unroll
        for (int o = 1; o < 8; o <<= 1) {
            int t = __shfl_up_sync(0xffffffffu, ws, o);
            if (lane >= o) ws += t;
        }
        if (lane < 8) wsum[lane] = ws;
    }
    __syncthreads();
    int run = sc - s + (w ? wsum[w - 1] : 0);  // exclusive prefix for this thread
#pragma unroll
    for (int j = 0; j < 4; j++) {
        run += v[j];
        if (base + j < NN) g_rowptr[base + j + 1] = run;  // block-local inclusive
    }
    if (tid == 255) g_bsum[blockIdx.x] = run;  // block total
}

// phase 2: scan the 49 block sums (one tiny block)
__global__ void k_scansums() {
    __shared__ int s[64];
    int tid = threadIdx.x;
    int v = (tid < NB) ? g_bsum[tid] : 0;
    s[tid] = v;
    __syncthreads();
    for (int o = 1; o < 64; o <<= 1) {
        int t = (tid >= o) ? s[tid - o] : 0;
        __syncthreads();
        s[tid] += t;
        __syncthreads();
    }
    if (tid < NB) g_boff[tid] = s[tid] - v;  // exclusive block offset
}

// phase 3: add offsets; derive cursor and dinv
__global__ void k_finalize() {
    int i = blockIdx.x * blockDim.x + threadIdx.x;
    if (i >= NN) return;
    int add = g_boff[i >> 10];
    int deg = g_degi[i];
    int r = g_rowptr[i + 1] + add;
    g_rowptr[i + 1] = r;
    g_cursor[i] = r - deg;
    g_dinv[i] = rsqrtf((float)deg);
    if (i == 0) g_rowptr[0] = 0;
}

__global__ void k_fill(const int* __restrict__ ei) {
    int e = blockIdx.x * blockDim.x + threadIdx.x;
    if (e >= ET) return;
    int src = (e < NE) ? ei[e]      : (e - NE);
    int dst = (e < NE) ? ei[NE + e] : (e - NE);
    int pos = atomicAdd(&g_cursor[dst], 1);
    g_csrc[pos] = src;
}

// ---------------- tf32 tensor-core GEMM: C[M,128] = A[M,128] @ W[128,128] ----
// BM=128, BN=128, BK=16. 256 threads = 8 warps in 4(M)x2(N); warp tile 32x64.
// mma.sync m16n8k8 tf32, fp32 accum. Fragment-packed smem: A frag = 1 LDS.128,
// B frag = 1 LDS.64, conflict-free. Output fp16 (for gathered buffers).

__device__ __forceinline__ uint32_t f2tf32(float x) {
    uint32_t r;
    asm("cvt.rna.tf32.f32 %0, %1;" : "=r"(r) : "f"(x));
    return r;
}

__device__ __forceinline__ void mma_tf32(float* c, const uint32_t* a, const uint32_t* b) {
    asm volatile(
        "mma.sync.aligned.m16n8k8.row.col.f32.tf32.tf32.f32 "
        "{%0,%1,%2,%3}, {%4,%5,%6,%7}, {%8,%9}, {%0,%1,%2,%3};"
        : "+f"(c[0]), "+f"(c[1]), "+f"(c[2]), "+f"(c[3])
        : "r"(a[0]), "r"(a[1]), "r"(a[2]), "r"(a[3]), "r"(b[0]), "r"(b[1]));
}

__global__ void __launch_bounds__(256) k_gemm(const float* __restrict__ A,
                                              const float* __restrict__ W,
                                              __half* __restrict__ C, int M) {
    __shared__ uint32_t As[2][8][32][4];
    __shared__ uint32_t Bs[2][16][32][2];
    const int tid = threadIdx.x;
    const int lane = tid & 31;
    const int warp = tid >> 5;
    const int wm = warp >> 1;       // 0..3
    const int wn = warp & 1;        // 0..1
    const int m0 = blockIdx.x * 128;

    float acc[2][8][4];
#pragma unroll
    for (int i = 0; i < 2; i++)
#pragma unroll
        for (int j = 0; j < 8; j++)
#pragma unroll
            for (int q = 0; q < 4; q++) acc[i][j][q] = 0.f;

    for (int k0 = 0; k0 < 128; k0 += 16) {
#pragma unroll
        for (int i = 0; i < 2; i++) {
            int f = tid * 2 + i;
            int row = f >> 2;
            int c4 = (f & 3) * 4;
            float4 v = make_float4(0.f, 0.f, 0.f, 0.f);
            if (m0 + row < M) v = *(const float4*)&A[(size_t)(m0 + row) * D + k0 + c4];
            int mf = row >> 4, mr = row & 15;
            float vv[4] = {v.x, v.y, v.z, v.w};
#pragma unroll
            for (int j = 0; j < 4; j++) {
                int k = c4 + j;
                int kf = k >> 3, kk = k & 7;
                As[kf][mf][(mr & 7) * 4 + (kk & 3)][(mr >> 3) | ((kk >> 2) << 1)] = f2tf32(vv[j]);
            }
        }
#pragma unroll
        for (int i = 0; i < 2; i++) {
            int f = tid * 2 + i;
            int kl = f >> 5;
            int n4 = (f & 31) * 4;
            float4 v = *(const float4*)&W[(size_t)(k0 + kl) * D + n4];
            int kf = kl >> 3, kk = kl & 7;
            float vv[4] = {v.x, v.y, v.z, v.w};
#pragma unroll
            for (int j = 0; j < 4; j++) {
                int n = n4 + j;
                Bs[kf][n >> 3][(n & 7) * 4 + (kk & 3)][kk >> 2] = f2tf32(vv[j]);
            }
        }
        __syncthreads();
#pragma unroll
        for (int kf = 0; kf < 2; kf++) {
            uint32_t afr[2][4];
#pragma unroll
            for (int mf = 0; mf < 2; mf++) {
                uint4 t = *(const uint4*)&As[kf][wm * 2 + mf][lane][0];
                afr[mf][0] = t.x; afr[mf][1] = t.y; afr[mf][2] = t.z; afr[mf][3] = t.w;
            }
            uint32_t bfr[8][2];
#pragma unroll
            for (int nf = 0; nf < 8; nf++) {
                uint2 t = *(const uint2*)&Bs[kf][wn * 8 + nf][lane][0];
                bfr[nf][0] = t.x; bfr[nf][1] = t.y;
            }
#pragma unroll
            for (int mf = 0; mf < 2; mf++)
#pragma unroll
                for (int nf = 0; nf < 8; nf++)
                    mma_tf32(acc[mf][nf], afr[mf], bfr[nf]);
        }
        __syncthreads();
    }

    // epilogue: fp16 store; c0,c1 at (g, q*2), c2,c3 at (g+8, q*2)
    const int g = lane >> 2, q = lane & 3;
#pragma unroll
    for (int mf = 0; mf < 2; mf++) {
        int row0 = m0 + wm * 32 + mf * 16 + g;
        int row1 = row0 + 8;
#pragma unroll
        for (int nf = 0; nf < 8; nf++) {
            int colh = wn * 32 + nf * 4 + q;   // half2 index within row
            if (row0 < M)
                ((__half2*)C)[(size_t)row0 * 64 + colh] = __floats2half2_rn(acc[mf][nf][0], acc[mf][nf][1]);
            if (row1 < M)
                ((__half2*)C)[(size_t)row1 * 64 + colh] = __floats2half2_rn(acc[mf][nf][2], acc[mf][nf][3]);
        }
    }
}

// ---------------- GCN aggregation (warp per dst, fp16 CSR gather) ----------------
__global__ void k_gcn_agg(const float* __restrict__ b) {
    int gt = blockIdx.x * blockDim.x + threadIdx.x;
    int n = gt >> 5, lane = gt & 31;
    if (n >= NN) return;
    const int start = g_rowptr[n], end = g_rowptr[n + 1];
    const float din = g_dinv[n];
    float4 acc = ((const float4*)b)[lane];
    for (int j0 = start; j0 < end; j0 += 32) {
        int jj = j0 + lane;
        int msrc = (jj < end) ? g_csrc[jj] : 0;
        float mnorm = (jj < end) ? g_dinv[msrc] * din : 0.f;
        int cnt = min(32, end - j0);
        for (int t = 0; t < cnt; t++) {
            int   s  = __shfl_sync(0xffffffffu, msrc, t);
            float nm = __shfl_sync(0xffffffffu, mnorm, t);
            uint2 u = ((const uint2*)g_xwh)[s * 32 + lane];   // 4 halves
            float2 f0 = __half22float2(*(__half2*)&u.x);
            float2 f1 = __half22float2(*(__half2*)&u.y);
            acc.x = fmaf(f0.x, nm, acc.x);
            acc.y = fmaf(f0.y, nm, acc.y);
            acc.z = fmaf(f1.x, nm, acc.z);
            acc.w = fmaf(f1.y, nm, acc.w);
        }
    }
    ((float4*)g_hgcn)[n * 32 + lane] = acc;
}

// ---------------- attention coefficients (reads fp16 xw2) ----------------
__global__ void k_attn(const float* __restrict__ ws, const float* __restrict__ wd) {
    int idx = blockIdx.x * blockDim.x + threadIdx.x;   // n*H + h
    if (idx >= NN * H) return;
    int n = idx >> 2, h = idx & 3;
    const __half2* xv = (const __half2*)&g_xw2h[(size_t)n * D + h * HD];
    const float* as = &ws[h * HD];
    const float* ad = &wd[h * HD];
    float s = 0.f, d = 0.f;
#pragma unroll
    for (int j = 0; j < 16; j++) {
        float2 x = __half22float2(xv[j]);
        s += x.x * as[2 * j] + x.y * as[2 * j + 1];
        d += x.x * ad[2 * j] + x.y * ad[2 * j + 1];
    }
    g_asrc[idx] = s;
    g_adst[idx] = d;
}

__device__ __forceinline__ float lrelu(float v) { return (v > 0.f) ? v : NEG * v; }

// ---------------- GAT + residual + LayerNorm + ReLU (warp per dst) ----------------
// Softmax without max-subtraction: logits are small (LN-bounded inputs), exp safe;
// exp(e)/sum(exp(e)) is mathematically identical to the max-subtracted form.
__global__ void k_gat_ln(const float* __restrict__ gb, const float* __restrict__ lg,
                         const float* __restrict__ lb, float* __restrict__ out) {
    __shared__ int    s_src[8][32];
    __shared__ float4 s_al[8][32];
    int gt = blockIdx.x * blockDim.x + threadIdx.x;
    int n = gt >> 5, lane = gt & 31, w = threadIdx.x >> 5;
    if (n >= NN) return;
    const int start = g_rowptr[n], end = g_rowptr[n + 1];
    const float4 ad = ((const float4*)g_adst)[n];

    // phase A: z per head (lane-parallel over edges)
    float z0 = 0.f, z1 = 0.f, z2 = 0.f, z3 = 0.f;
    for (int j = start + lane; j < end; j += 32) {
        int src = g_csrc[j];
        float4 as = ((const float4*)g_asrc)[src];
        z0 += __expf(lrelu(as.x + ad.x));
        z1 += __expf(lrelu(as.y + ad.y));
        z2 += __expf(lrelu(as.z + ad.z));
        z3 += __expf(lrelu(as.w + ad.w));
    }
#pragma unroll
    for (int o = 16; o; o >>= 1) {
        z0 += __shfl_xor_sync(0xffffffffu, z0, o);
        z1 += __shfl_xor_sync(0xffffffffu, z1, o);
        z2 += __shfl_xor_sync(0xffffffffu, z2, o);
        z3 += __shfl_xor_sync(0xffffffffu, z3, o);
    }
    const float r0 = 1.f / z0, r1 = 1.f / z1, r2 = 1.f / z2, r3 = 1.f / z3;

    // phase B: weighted fp16 gather in 32-edge chunks
    float4 acc = ((const float4*)gb)[lane];
    for (int j0 = start; j0 < end; j0 += 32) {
        int jj = j0 + lane;
        if (jj < end) {
            int src = g_csrc[jj];
            float4 as = ((const float4*)g_asrc)[src];
            float4 al;
            al.x = __expf(lrelu(as.x + ad.x)) * r0;
            al.y = __expf(lrelu(as.y + ad.y)) * r1;
            al.z = __expf(lrelu(as.z + ad.z)) * r2;
            al.w = __expf(lrelu(as.w + ad.w)) * r3;
            s_src[w][lane] = src;
            s_al[w][lane] = al;
        }
        __syncwarp();
        int cnt = min(32, end - j0);
        for (int t = 0; t < cnt; t++) {
            int src = s_src[w][t];
            float a = ((const float*)&s_al[w][t])[lane >> 3];
            uint2 u = ((const uint2*)g_xw2h)[src * 32 + lane];   // 4 halves
            float2 f0 = __half22float2(*(__half2*)&u.x);
            float2 f1 = __half22float2(*(__half2*)&u.y);
            acc.x = fmaf(f0.x, a, acc.x);
            acc.y = fmaf(f0.y, a, acc.y);
            acc.z = fmaf(f1.x, a, acc.z);
            acc.w = fmaf(f1.y, a, acc.w);
        }
        __syncwarp();
    }

    // residual + LayerNorm + ReLU
    float4 c = ((const float4*)g_hgcn)[n * 32 + lane];
    acc.x += c.x; acc.y += c.y; acc.z += c.z; acc.w += c.w;
    float s = acc.x + acc.y + acc.z + acc.w;
#pragma unroll
    for (int o = 16; o; o >>= 1) s += __shfl_xor_sync(0xffffffffu, s, o);
    float mu = s * (1.0f / D);
    float dx = acc.x - mu, dy = acc.y - mu, dz = acc.z - mu, dw = acc.w - mu;
    float q = dx * dx + dy * dy + dz * dz + dw * dw;
#pragma unroll
    for (int o = 16; o; o >>= 1) q += __shfl_xor_sync(0xffffffffu, q, o);
    float rs = rsqrtf(q * (1.0f / D) + 1e-5f);
    float4 gg = ((const float4*)lg)[lane];
    float4 bb = ((const float4*)lb)[lane];
    float4 y;
    y.x = fmaxf(dx * rs * gg.x + bb.x, 0.f);
    y.y = fmaxf(dy * rs * gg.y + bb.y, 0.f);
    y.z = fmaxf(dz * rs * gg.z + bb.z, 0.f);
    y.w = fmaxf(dw * rs * gg.w + bb.w, 0.f);
    ((float4*)out)[n * 32 + lane] = y;
}

// ---------------- launch ----------------
extern "C" void kernel_launch(void* const* d_in, const int* in_sizes, int n_in,
                              void* d_out, int out_size) {
    const float* x      = (const float*)d_in[0];
    const int*   ei     = (const int*)  d_in[1];
    const float* gcn_w  = (const float*)d_in[2];
    const float* gcn_b  = (const float*)d_in[3];
    const float* gat_w  = (const float*)d_in[4];
    const float* att_s  = (const float*)d_in[5];
    const float* att_d  = (const float*)d_in[6];
    const float* gat_b  = (const float*)d_in[7];
    const float* ln_g   = (const float*)d_in[8];
    const float* ln_b   = (const float*)d_in[9];
    float* out = (float*)d_out;

    float  *p_h, *p_hgcn;
    __half *p_xwh, *p_xw2h;
    cudaGetSymbolAddress((void**)&p_h,     g_h);
    cudaGetSymbolAddress((void**)&p_hgcn,  g_hgcn);
    cudaGetSymbolAddress((void**)&p_xwh,   g_xwh);
    cudaGetSymbolAddress((void**)&p_xw2h,  g_xw2h);

    const int T = 256;
    // CSR build (per replay; graph-capturable, no allocation)
    k_zerodeg<<<cdiv(NN, T), T>>>();
    k_deg<<<cdiv(ET, T), T>>>(ei);
    k_blockscan<<<NB, 256>>>();
    k_scansums<<<1, 64>>>();
    k_finalize<<<cdiv(NN, T), T>>>();
    k_fill<<<cdiv(ET, T), T>>>(ei);

    const float* hin = x;
    for (int l = 0; l < 3; l++) {
        // GCN
        k_gemm<<<cdiv(NN, 128), T>>>(hin, gcn_w + l * D * D, p_xwh, NN);
        k_gcn_agg<<<cdiv(NN * 32, T), T>>>(gcn_b + l * D);
        // GAT
        k_gemm<<<cdiv(NN, 128), T>>>(p_hgcn, gat_w + l * D * D, p_xw2h, NN);
        k_attn<<<cdiv(NN * H, T), T>>>(att_s + l * H * HD, att_d + l * H * HD);
        // GAT aggregation + residual + LN + ReLU fused
        float* o = (l == 2) ? out : p_h;
        k_gat_ln<<<cdiv(NN * 32, T), T>>>(gat_b + l * D, ln_g + l * D, ln_b + l * D, o);
        hin = p_h;
    }
}